// round 5
// baseline (speedup 1.0000x reference)
#include <cuda_runtime.h>
#include <cstdint>

// ============================================================================
// quan_Linear_fi: exact reproduction of JAX reference (PARTITIONABLE threefry).
//   B=2, S=128, IN=512, OUT=512, BITS=8 (weight quant), FI width=16, BER=1e-5
//
// JAX (jax_threefry_partitionable=True, default since 0.4.36) random_bits for
// 32-bit width:  bits[j] = o0 ^ o1  where (o0,o1) = threefry2x32(key, (0, j)).
// bernoulli(1e-5): bitcast((bits>>9)|0x3f800000)-1 < 1e-5f  <=>  bits < 43008.
// fold_in(key, d) = threefry2x32(key, (0, d))  -> compile-time subkeys
// (fold_in uses the raw block cipher regardless of the partitionable flag).
// ============================================================================

#define HALF_N  (1u << 25)   // batch stride in the p/c tensor [2,512,128,512]

__device__ float    g_wq[512 * 512];
__device__ float    g_c[1u << 26];       // 256 MiB scratch: faulty-cumsum tensor
__device__ float    g_y[2 * 512 * 128];
__device__ unsigned g_wmax, g_pmax, g_cmax, g_ymax;

// ---------------------------------------------------------------------------
// threefry2x32 (JAX-exact): compile-time version for subkey derivation
// ---------------------------------------------------------------------------
struct U2c { unsigned a, b; };

__host__ __device__ constexpr unsigned rotl_c(unsigned x, int d) {
    return (x << d) | (x >> (32 - d));
}

__host__ __device__ constexpr U2c tf_c(unsigned k0, unsigned k1,
                                       unsigned x0, unsigned x1) {
    unsigned ks2 = k0 ^ k1 ^ 0x1BD11BDAu;
    const int RA[4] = {13, 15, 26, 6};
    const int RB[4] = {17, 29, 16, 24};
    x0 += k0;  x1 += k1;
    for (int i = 0; i < 4; i++) { x0 += x1; x1 = rotl_c(x1, RA[i]); x1 ^= x0; }
    x0 += k1;  x1 += ks2 + 1u;
    for (int i = 0; i < 4; i++) { x0 += x1; x1 = rotl_c(x1, RB[i]); x1 ^= x0; }
    x0 += ks2; x1 += k0 + 2u;
    for (int i = 0; i < 4; i++) { x0 += x1; x1 = rotl_c(x1, RA[i]); x1 ^= x0; }
    x0 += k0;  x1 += k1 + 3u;
    for (int i = 0; i < 4; i++) { x0 += x1; x1 = rotl_c(x1, RB[i]); x1 ^= x0; }
    x0 += k1;  x1 += ks2 + 4u;
    for (int i = 0; i < 4; i++) { x0 += x1; x1 = rotl_c(x1, RA[i]); x1 ^= x0; }
    x0 += ks2; x1 += k0 + 5u;
    return U2c{x0, x1};
}

// subkey(stage s, bit b) = fold_in(fold_in(key(42), s), b); key(42) = (0, 42)
__host__ __device__ constexpr U2c subkey_c(int s, int b) {
    U2c ks = tf_c(0u, 42u, 0u, (unsigned)s);
    return tf_c(ks.a, ks.b, 0u, (unsigned)b);
}

// ---------------------------------------------------------------------------
// Runtime threefry block; keys are compile-time immediates at call sites.
// Returns o0 ^ o1 (the partitionable 32-bit random_bits combination).
// ---------------------------------------------------------------------------
#define TF_RND(r) { x0 += x1; x1 = __funnelshift_l(x1, x1, (r)); x1 ^= x0; }

__device__ __forceinline__ unsigned tf_xor(unsigned k0, unsigned k1,
                                           unsigned x1) {
    unsigned ks2 = k0 ^ k1 ^ 0x1BD11BDAu;
    unsigned x0 = k0;          // x0 starts at 0 (counts hi word) + k0
    x1 += k1;
    TF_RND(13) TF_RND(15) TF_RND(26) TF_RND(6)
    x0 += k1;  x1 += ks2 + 1u;
    TF_RND(17) TF_RND(29) TF_RND(16) TF_RND(24)
    x0 += ks2; x1 += k0 + 2u;
    TF_RND(13) TF_RND(15) TF_RND(26) TF_RND(6)
    x0 += k0;  x1 += k1 + 3u;
    TF_RND(17) TF_RND(29) TF_RND(16) TF_RND(24)
    x0 += k1;  x1 += ks2 + 4u;
    TF_RND(13) TF_RND(15) TF_RND(26) TF_RND(6)
    x0 += ks2; x1 += k0 + 5u;
    return x0 ^ x1;
}

// Build 16-bit flip masks for 4 independent element indices (ILP x4).
template <int S, int Bit>
__device__ __forceinline__ void mask4(const unsigned j[4], unsigned m[4]) {
    if constexpr (Bit < 16) {
        constexpr U2c K = subkey_c(S, Bit);
        #pragma unroll
        for (int i = 0; i < 4; i++)
            if (tf_xor(K.a, K.b, j[i]) < 43008u) m[i] |= (1u << Bit);
        mask4<S, Bit + 1>(j, m);
    }
}

template <int S, int Bit>
__device__ __forceinline__ void mask2(unsigned j0, unsigned j1,
                                      unsigned& m0, unsigned& m1) {
    if constexpr (Bit < 16) {
        constexpr U2c K = subkey_c(S, Bit);
        if (tf_xor(K.a, K.b, j0) < 43008u) m0 |= (1u << Bit);
        if (tf_xor(K.a, K.b, j1) < 43008u) m1 |= (1u << Bit);
        mask2<S, Bit + 1>(j0, j1, m0, m1);
    }
}

// _bitflip_fi forward: quantize to 16-bit offset-binary, XOR mask, dequantize.
__device__ __forceinline__ float fi_q(float t, float sc, unsigned mask) {
    float r = rintf(__fdiv_rn(t, sc));             // jnp.round: half-to-even
    r = fminf(fmaxf(r, -32768.0f), 32767.0f);      // clip(-(n+1), n)
    int q  = (int)r;
    int q2 = (int)(((unsigned)(q + 32768)) ^ mask) - 32768;
    return __fmul_rn((float)q2, sc);
}

__device__ __forceinline__ float load_scale(const unsigned& g) {
    float sc = __fdiv_rn(__uint_as_float(g), 32767.0f);
    if (!(sc > 0.0f)) sc = 1.0f;                   // where(scale>0, scale, 1)
    return sc;
}

// ---------------------------------------------------------------------------
__global__ void k_init() { g_wmax = 0; g_pmax = 0; g_cmax = 0; g_ymax = 0; }

__global__ void k_wmax(const float* __restrict__ w, int n) {
    float m = 0.0f;
    for (int i = blockIdx.x * blockDim.x + threadIdx.x; i < n;
         i += gridDim.x * blockDim.x)
        m = fmaxf(m, fabsf(w[i]));
    #pragma unroll
    for (int off = 16; off; off >>= 1)
        m = fmaxf(m, __shfl_xor_sync(0xffffffffu, m, off));
    if ((threadIdx.x & 31) == 0) atomicMax(&g_wmax, __float_as_uint(m));
}

// One block per input-feature k. Quantizes w column; computes
// pmax = max_k( max_{b,s}|x[.,.,k]| * max_o|wq[o,k]| ) — exact for max|x*wq|
// (fl() is monotone, so the max of rounded products is the rounded max product).
__global__ void k_wq(const float* __restrict__ w, const float* __restrict__ x) {
    const int k = blockIdx.x;        // 0..511
    const int t = threadIdx.x;       // 0..255
    const float step = __fdiv_rn(__uint_as_float(g_wmax), 127.0f);
    float lmw = 0.0f;
    for (int o = t; o < 512; o += 256) {
        float wv = w[o * 512 + k];
        float r  = rintf(__fdiv_rn(wv, step));
        r = fminf(fmaxf(r, -128.0f), 127.0f);
        float wq = __fmul_rn(r, step);
        g_wq[o * 512 + k] = wq;
        lmw = fmaxf(lmw, fabsf(wq));
    }
    float lmx = fabsf(x[t * 512 + k]);   // t enumerates (b*128+s), 256 values
    __shared__ float smw[256], smx[256];
    smw[t] = lmw; smx[t] = lmx;
    __syncthreads();
    for (int off = 128; off; off >>= 1) {
        if (t < off) {
            smw[t] = fmaxf(smw[t], smw[t + off]);
            smx[t] = fmaxf(smx[t], smx[t + off]);
        }
        __syncthreads();
    }
    if (t == 0)
        atomicMax(&g_pmax, __float_as_uint(__fmul_rn(smx[0], smw[0])));
}

// Stage 0: p = x*wq -> bitflip_fi(0) -> cumsum over k -> g_c ; reduce cmax.
// One thread per (o, s); handles b=0 and b=1 and k-unroll-2 (4 PRNG chains).
__global__ void __launch_bounds__(128) k_stage0(const float* __restrict__ x) {
    const unsigned tid = blockIdx.x * 128u + threadIdx.x;   // < 65536
    const unsigned o = tid >> 7, s = tid & 127u;
    const float sp = load_scale(g_pmax);
    const float* __restrict__ x0p = x + s * 512;            // b=0
    const float* __restrict__ x1p = x + (128 + s) * 512;    // b=1
    const float* __restrict__ wqp = g_wq + o * 512;
    const unsigned jb = tid * 512u;                         // (o*128+s)*512
    float* __restrict__ c0p = g_c + jb;
    float* __restrict__ c1p = g_c + jb + HALF_N;
    float c0 = 0.0f, c1 = 0.0f, cm = 0.0f;
    for (int k = 0; k < 512; k += 2) {
        unsigned j[4] = { jb + k, jb + k + 1u,
                          jb + k + HALF_N, jb + k + 1u + HALF_N };
        unsigned m[4] = { 0, 0, 0, 0 };
        mask4<0, 0>(j, m);
        float p00 = __fmul_rn(x0p[k],     wqp[k]);
        float p01 = __fmul_rn(x0p[k + 1], wqp[k + 1]);
        float p10 = __fmul_rn(x1p[k],     wqp[k]);
        float p11 = __fmul_rn(x1p[k + 1], wqp[k + 1]);
        c0 = __fadd_rn(c0, fi_q(p00, sp, m[0])); c0p[k]     = c0;
        cm = fmaxf(cm, fabsf(c0));
        c0 = __fadd_rn(c0, fi_q(p01, sp, m[1])); c0p[k + 1] = c0;
        cm = fmaxf(cm, fabsf(c0));
        c1 = __fadd_rn(c1, fi_q(p10, sp, m[2])); c1p[k]     = c1;
        cm = fmaxf(cm, fabsf(c1));
        c1 = __fadd_rn(c1, fi_q(p11, sp, m[3])); c1p[k + 1] = c1;
        cm = fmaxf(cm, fabsf(c1));
    }
    #pragma unroll
    for (int off = 16; off; off >>= 1)
        cm = fmaxf(cm, __shfl_xor_sync(0xffffffffu, cm, off));
    if ((threadIdx.x & 31) == 0) atomicMax(&g_cmax, __float_as_uint(cm));
}

// Stage 1: c -> bitflip_fi(1); y = c_fi[511] + sum_{k=1..510}(c_fi[k]-c[k]).
// k-loop unrolled by 2: even slot k (excluded only at k=0), odd slot k+1
// (the k+1==511 case is y_sum, not c_error).
__global__ void __launch_bounds__(128) k_stage1() {
    const unsigned tid = blockIdx.x * 128u + threadIdx.x;   // < 65536
    const float sc = load_scale(g_cmax);
    const unsigned jb = tid * 512u;
    const float* __restrict__ c0p = g_c + jb;
    const float* __restrict__ c1p = g_c + jb + HALF_N;
    float a0 = 0.0f, a1 = 0.0f, y0 = 0.0f, y1 = 0.0f;
    for (int k = 0; k < 512; k += 2) {
        unsigned j[4] = { jb + k, jb + k + 1u,
                          jb + k + HALF_N, jb + k + 1u + HALF_N };
        unsigned m[4] = { 0, 0, 0, 0 };
        mask4<1, 0>(j, m);
        float c00 = c0p[k], c01 = c0p[k + 1];
        float c10 = c1p[k], c11 = c1p[k + 1];
        float f00 = fi_q(c00, sc, m[0]);
        float f01 = fi_q(c01, sc, m[1]);
        float f10 = fi_q(c10, sc, m[2]);
        float f11 = fi_q(c11, sc, m[3]);
        if (k > 0) {                     // even slot, interior (k=2..510)
            a0 = __fadd_rn(a0, __fsub_rn(f00, c00));
            a1 = __fadd_rn(a1, __fsub_rn(f10, c10));
        }
        if (k + 1 == 511) {              // odd slot, last element: y_sum
            y0 = f01;
            y1 = f11;
        } else {                         // odd slot, interior (k+1=1..509)
            a0 = __fadd_rn(a0, __fsub_rn(f01, c01));
            a1 = __fadd_rn(a1, __fsub_rn(f11, c11));
        }
    }
    y0 = __fadd_rn(y0, a0);              // y_sum + c_error
    y1 = __fadd_rn(y1, a1);
    g_y[tid]          = y0;              // y layout [B,OUT,S]: b*65536+o*128+s
    g_y[tid + 65536u] = y1;
    float ym = fmaxf(fabsf(y0), fabsf(y1));
    #pragma unroll
    for (int off = 16; off; off >>= 1)
        ym = fmaxf(ym, __shfl_xor_sync(0xffffffffu, ym, off));
    if ((threadIdx.x & 31) == 0) atomicMax(&g_ymax, __float_as_uint(ym));
}

// Stage 2: bitflip_fi(2) on y [2,512,128]; transpose -> [B,S,OUT], add bias.
__global__ void k_stage2(const float* __restrict__ bias,
                         float* __restrict__ out) {
    const unsigned tid = blockIdx.x * blockDim.x + threadIdx.x;  // < 65536
    const unsigned o = tid >> 7, s = tid & 127u;
    const float sy = load_scale(g_ymax);
    unsigned m0 = 0, m1 = 0;
    mask2<2, 0>(tid, tid + 65536u, m0, m1);
    float y0 = g_y[tid], y1 = g_y[tid + 65536u];
    float bv = bias[o];
    out[s * 512u + o]          = __fadd_rn(fi_q(y0, sy, m0), bv);  // b=0
    out[65536u + s * 512u + o] = __fadd_rn(fi_q(y1, sy, m1), bv);  // b=1
}

// ---------------------------------------------------------------------------
extern "C" void kernel_launch(void* const* d_in, const int* in_sizes, int n_in,
                              void* d_out, int out_size) {
    const float* x    = (const float*)d_in[0];   // [2,128,512]
    const float* w    = (const float*)d_in[1];   // [512,512]
    const float* bias = (const float*)d_in[2];   // [512]
    float* out = (float*)d_out;                  // [2,128,512]

    k_init<<<1, 1>>>();
    k_wmax<<<64, 256>>>(w, 512 * 512);
    k_wq<<<512, 256>>>(w, x);
    k_stage0<<<512, 128>>>(x);
    k_stage1<<<512, 128>>>();
    k_stage2<<<256, 256>>>(bias, out);
}

// round 6
// speedup vs baseline: 1.2570x; 1.2570x over previous
#include <cuda_runtime.h>
#include <cstdint>

// ============================================================================
// quan_Linear_fi: exact reproduction of JAX reference (PARTITIONABLE threefry).
//   B=2, S=128, IN=512, OUT=512, BITS=8 (weight quant), FI width=16, BER=1e-5
//
// random_bits (partitionable): bits[j] = o0^o1, (o0,o1)=threefry2x32(key,(0,j))
// bernoulli(1e-5): bits < 43008.  fold_in = raw cipher -> compile-time subkeys.
//
// R6 perf changes vs R5 (values bit-identical):
//  - thread per (b,o,s): 131072 threads (occ 21% -> 43%)
//  - round-adds forced to IMAD (fma pipe) via opaque `one` -> alu offload
//  - g_c transposed to [k][chain], wq to [k][o]: fully coalesced; x broadcast
// ============================================================================

#define HALF_N   (1u << 25)    // batch stride in logical p/c tensor [2,512,128,512]
#define NCHAIN   131072u       // 2*512*128 cumsum chains

__device__ float    g_wq[512 * 512];     // transposed: [k][o]
__device__ float    g_c[1u << 26];       // [k][chain], chain = b*65536+s*512+o
__device__ float    g_y[2 * 512 * 128];  // [b][s][o]
__device__ unsigned g_wmax, g_pmax, g_cmax, g_ymax, g_one;

// ---------------------------------------------------------------------------
// threefry2x32 (JAX-exact): compile-time version for subkey derivation
// ---------------------------------------------------------------------------
struct U2c { unsigned a, b; };

__host__ __device__ constexpr unsigned rotl_c(unsigned x, int d) {
    return (x << d) | (x >> (32 - d));
}

__host__ __device__ constexpr U2c tf_c(unsigned k0, unsigned k1,
                                       unsigned x0, unsigned x1) {
    unsigned ks2 = k0 ^ k1 ^ 0x1BD11BDAu;
    const int RA[4] = {13, 15, 26, 6};
    const int RB[4] = {17, 29, 16, 24};
    x0 += k0;  x1 += k1;
    for (int i = 0; i < 4; i++) { x0 += x1; x1 = rotl_c(x1, RA[i]); x1 ^= x0; }
    x0 += k1;  x1 += ks2 + 1u;
    for (int i = 0; i < 4; i++) { x0 += x1; x1 = rotl_c(x1, RB[i]); x1 ^= x0; }
    x0 += ks2; x1 += k0 + 2u;
    for (int i = 0; i < 4; i++) { x0 += x1; x1 = rotl_c(x1, RA[i]); x1 ^= x0; }
    x0 += k0;  x1 += k1 + 3u;
    for (int i = 0; i < 4; i++) { x0 += x1; x1 = rotl_c(x1, RB[i]); x1 ^= x0; }
    x0 += k1;  x1 += ks2 + 4u;
    for (int i = 0; i < 4; i++) { x0 += x1; x1 = rotl_c(x1, RA[i]); x1 ^= x0; }
    x0 += ks2; x1 += k0 + 5u;
    return U2c{x0, x1};
}

// subkey(stage s, bit b) = fold_in(fold_in(key(42), s), b); key(42) = (0, 42)
__host__ __device__ constexpr U2c subkey_c(int s, int b) {
    U2c ks = tf_c(0u, 42u, 0u, (unsigned)s);
    return tf_c(ks.a, ks.b, 0u, (unsigned)b);
}

// ---------------------------------------------------------------------------
// Runtime threefry block. Round adds forced onto the fma pipe (IMAD) via the
// opaque multiplier `one` (==1, loaded from g_one; ptxas cannot fold it).
// SHF + LOP3 stay on the alu pipe -> ~48 alu + ~25 fma per block (vs 57:15).
// ---------------------------------------------------------------------------
#define TF_RND_F(r) {                                                         \
    asm("mad.lo.u32 %0, %1, %2, %0;" : "+r"(x0) : "r"(x1), "r"(one));         \
    x1 = __funnelshift_l(x1, x1, (r));                                        \
    x1 ^= x0; }

__device__ __forceinline__ unsigned tf_xor_f(unsigned k0, unsigned k1,
                                             unsigned x1, unsigned one) {
    unsigned ks2 = k0 ^ k1 ^ 0x1BD11BDAu;   // constant-folded per call site
    unsigned x0 = k0;                       // counts hi word (0) + k0
    x1 += k1;
    TF_RND_F(13) TF_RND_F(15) TF_RND_F(26) TF_RND_F(6)
    x0 += k1;  x1 += ks2 + 1u;
    TF_RND_F(17) TF_RND_F(29) TF_RND_F(16) TF_RND_F(24)
    x0 += ks2; x1 += k0 + 2u;
    TF_RND_F(13) TF_RND_F(15) TF_RND_F(26) TF_RND_F(6)
    x0 += k0;  x1 += k1 + 3u;
    TF_RND_F(17) TF_RND_F(29) TF_RND_F(16) TF_RND_F(24)
    x0 += k1;  x1 += ks2 + 4u;
    TF_RND_F(13) TF_RND_F(15) TF_RND_F(26) TF_RND_F(6)
    x0 += ks2; x1 += k0 + 5u;
    return x0 ^ x1;
}

// Build 16-bit flip masks for 2 independent element indices (ILP x2).
template <int S, int Bit>
__device__ __forceinline__ void mask2f(unsigned j0, unsigned j1,
                                       unsigned& m0, unsigned& m1,
                                       unsigned one) {
    if constexpr (Bit < 16) {
        constexpr U2c K = subkey_c(S, Bit);
        if (tf_xor_f(K.a, K.b, j0, one) < 43008u) m0 |= (1u << Bit);
        if (tf_xor_f(K.a, K.b, j1, one) < 43008u) m1 |= (1u << Bit);
        mask2f<S, Bit + 1>(j0, j1, m0, m1, one);
    }
}

// _bitflip_fi forward: quantize to 16-bit offset-binary, XOR mask, dequantize.
__device__ __forceinline__ float fi_q(float t, float sc, unsigned mask) {
    float r = rintf(__fdiv_rn(t, sc));             // jnp.round: half-to-even
    r = fminf(fmaxf(r, -32768.0f), 32767.0f);      // clip(-(n+1), n)
    int q  = (int)r;
    int q2 = (int)(((unsigned)(q + 32768)) ^ mask) - 32768;
    return __fmul_rn((float)q2, sc);
}

__device__ __forceinline__ float load_scale(const unsigned& g) {
    float sc = __fdiv_rn(__uint_as_float(g), 32767.0f);
    if (!(sc > 0.0f)) sc = 1.0f;                   // where(scale>0, scale, 1)
    return sc;
}

// ---------------------------------------------------------------------------
__global__ void k_init() {
    g_wmax = 0; g_pmax = 0; g_cmax = 0; g_ymax = 0; g_one = 1u;
}

__global__ void k_wmax(const float* __restrict__ w, int n) {
    float m = 0.0f;
    for (int i = blockIdx.x * blockDim.x + threadIdx.x; i < n;
         i += gridDim.x * blockDim.x)
        m = fmaxf(m, fabsf(w[i]));
    #pragma unroll
    for (int off = 16; off; off >>= 1)
        m = fmaxf(m, __shfl_xor_sync(0xffffffffu, m, off));
    if ((threadIdx.x & 31) == 0) atomicMax(&g_wmax, __float_as_uint(m));
}

// One block per input-feature k. Quantizes w column into TRANSPOSED g_wq[k][o];
// pmax = max_k( max_{b,s}|x[.,.,k]| * max_o|wq[o,k]| ) — exact for max|x*wq|.
__global__ void k_wq(const float* __restrict__ w, const float* __restrict__ x) {
    const int k = blockIdx.x;        // 0..511
    const int t = threadIdx.x;       // 0..255
    const float step = __fdiv_rn(__uint_as_float(g_wmax), 127.0f);
    float lmw = 0.0f;
    for (int o = t; o < 512; o += 256) {
        float wv = w[o * 512 + k];
        float r  = rintf(__fdiv_rn(wv, step));
        r = fminf(fmaxf(r, -128.0f), 127.0f);
        float wq = __fmul_rn(r, step);
        g_wq[k * 512 + o] = wq;                  // transposed, coalesced store
        lmw = fmaxf(lmw, fabsf(wq));
    }
    float lmx = fabsf(x[t * 512 + k]);   // t enumerates (b*128+s), 256 values
    __shared__ float smw[256], smx[256];
    smw[t] = lmw; smx[t] = lmx;
    __syncthreads();
    for (int off = 128; off; off >>= 1) {
        if (t < off) {
            smw[t] = fmaxf(smw[t], smw[t + off]);
            smx[t] = fmaxf(smx[t], smx[t + off]);
        }
        __syncthreads();
    }
    if (t == 0)
        atomicMax(&g_pmax, __float_as_uint(__fmul_rn(smx[0], smw[0])));
}

// Stage 0: p = x*wq -> bitflip_fi(0) -> cumsum over k -> g_c ; reduce cmax.
// One thread per (b,s,o): tid = b*65536 + s*512 + o (lanes vary o).
//   x[(b*128+s)*512+k]      : warp-uniform broadcast
//   g_wq[k*512+o]           : coalesced
//   g_c[k*NCHAIN+tid]       : coalesced
// Logical p-index: j = b*HALF_N + o*65536 + s*512 + k.
__global__ void __launch_bounds__(256) k_stage0(const float* __restrict__ x) {
    const unsigned tid = blockIdx.x * 256u + threadIdx.x;   // < 131072
    const unsigned o = tid & 511u, s = (tid >> 9) & 127u, b = tid >> 16;
    const unsigned one = g_one;
    const float sp = load_scale(g_pmax);
    const float* __restrict__ xp = x + (b * 128u + s) * 512u;
    const unsigned jb = b * HALF_N + o * 65536u + s * 512u;
    float c = 0.0f, cm = 0.0f;
    for (int k = 0; k < 512; k += 2) {
        unsigned m0 = 0, m1 = 0;
        mask2f<0, 0>(jb + k, jb + k + 1u, m0, m1, one);
        float2 xv = *(const float2*)(xp + k);               // uniform
        float w0 = g_wq[k * 512 + o];
        float w1 = g_wq[(k + 1) * 512 + o];
        float p0 = __fmul_rn(xv.x, w0);
        float p1 = __fmul_rn(xv.y, w1);
        c = __fadd_rn(c, fi_q(p0, sp, m0));
        g_c[(unsigned)k * NCHAIN + tid] = c;
        cm = fmaxf(cm, fabsf(c));
        c = __fadd_rn(c, fi_q(p1, sp, m1));
        g_c[(unsigned)(k + 1) * NCHAIN + tid] = c;
        cm = fmaxf(cm, fabsf(c));
    }
    #pragma unroll
    for (int off = 16; off; off >>= 1)
        cm = fmaxf(cm, __shfl_xor_sync(0xffffffffu, cm, off));
    if ((threadIdx.x & 31) == 0) atomicMax(&g_cmax, __float_as_uint(cm));
}

// Stage 1: c -> bitflip_fi(1); y = c_fi[511] + sum_{k=1..510}(c_fi[k]-c[k]).
// Same thread mapping as stage 0; stores y in [b][s][o] (= g_y[tid]).
__global__ void __launch_bounds__(256) k_stage1() {
    const unsigned tid = blockIdx.x * 256u + threadIdx.x;   // < 131072
    const unsigned o = tid & 511u, s = (tid >> 9) & 127u, b = tid >> 16;
    const unsigned one = g_one;
    const float sc = load_scale(g_cmax);
    const unsigned jb = b * HALF_N + o * 65536u + s * 512u;
    float a = 0.0f, y = 0.0f;
    for (int k = 0; k < 512; k += 2) {
        unsigned m0 = 0, m1 = 0;
        mask2f<1, 0>(jb + k, jb + k + 1u, m0, m1, one);
        float c0 = g_c[(unsigned)k * NCHAIN + tid];
        float c1 = g_c[(unsigned)(k + 1) * NCHAIN + tid];
        float f0 = fi_q(c0, sc, m0);
        float f1 = fi_q(c1, sc, m1);
        if (k > 0)                      // even slot interior (k = 2..510)
            a = __fadd_rn(a, __fsub_rn(f0, c0));
        if (k + 1 == 511)               // odd slot, last element: y_sum
            y = f1;
        else                            // odd slot interior (k+1 = 1..509)
            a = __fadd_rn(a, __fsub_rn(f1, c1));
    }
    y = __fadd_rn(y, a);                // y_sum + c_error
    g_y[tid] = y;                       // [b][s][o]
    float ym = fabsf(y);
    #pragma unroll
    for (int off = 16; off; off >>= 1)
        ym = fmaxf(ym, __shfl_xor_sync(0xffffffffu, ym, off));
    if ((threadIdx.x & 31) == 0) atomicMax(&g_ymax, __float_as_uint(ym));
}

// Stage 2: bitflip_fi(2) on logical y [2,512,128]; output [B,S,OUT] + bias.
// Thread t = s*512 + o handles both batches; logical j0 = o*128+s, j1 = j0+65536.
__global__ void k_stage2(const float* __restrict__ bias,
                         float* __restrict__ out) {
    const unsigned t = blockIdx.x * blockDim.x + threadIdx.x;    // < 65536
    const unsigned o = t & 511u, s = t >> 9;
    const unsigned one = g_one;
    const float sy = load_scale(g_ymax);
    const unsigned j0 = o * 128u + s;
    unsigned m0 = 0, m1 = 0;
    mask2f<2, 0>(j0, j0 + 65536u, m0, m1, one);
    float y0 = g_y[t];                  // [b=0][s][o]
    float y1 = g_y[t + 65536u];         // [b=1][s][o]
    float bv = bias[o];
    out[t]           = __fadd_rn(fi_q(y0, sy, m0), bv);
    out[t + 65536u]  = __fadd_rn(fi_q(y1, sy, m1), bv);
}

// ---------------------------------------------------------------------------
extern "C" void kernel_launch(void* const* d_in, const int* in_sizes, int n_in,
                              void* d_out, int out_size) {
    const float* x    = (const float*)d_in[0];   // [2,128,512]
    const float* w    = (const float*)d_in[1];   // [512,512]
    const float* bias = (const float*)d_in[2];   // [512]
    float* out = (float*)d_out;                  // [2,128,512]

    k_init<<<1, 1>>>();
    k_wmax<<<64, 256>>>(w, 512 * 512);
    k_wq<<<512, 256>>>(w, x);
    k_stage0<<<512, 256>>>(x);
    k_stage1<<<512, 256>>>();
    k_stage2<<<256, 256>>>(bias, out);
}